// round 12
// baseline (speedup 1.0000x reference)
#include <cuda_runtime.h>
#include <cuda_fp16.h>
#include <cstdint>

// Shapes (fixed): B=4, S=2048, D=1024, H=16, dk=64.
#define MDIM 8192
#define NDIM 1024
#define KDIM 1024

// ---------------------------------------------------------------------------
// Device scratch (allocation-free per harness rules)
// ---------------------------------------------------------------------------
__device__ __half g_X[3][MDIM * NDIM];    // fp16 activations (slot 0 reused for ctx)
__device__ __half g_WT[4][NDIM * KDIM];   // transposed weights, fp16
__device__ __half g_Qh[MDIM * NDIM];      // fp16 projections for attention
__device__ __half g_Kh[MDIM * NDIM];
__device__ __half g_Vh[MDIM * NDIM];

// ---------------------------------------------------------------------------
// Helpers
// ---------------------------------------------------------------------------
__device__ __forceinline__ uint32_t smem_u32(const void* p) {
    uint32_t a;
    asm("{ .reg .u64 t; cvta.to.shared.u64 t, %1; cvt.u32.u64 %0, t; }"
        : "=r"(a) : "l"(p));
    return a;
}

__device__ __forceinline__ void mma_f16(float* c, const uint32_t* a,
                                        uint32_t b0, uint32_t b1) {
    asm volatile(
        "mma.sync.aligned.m16n8k16.row.col.f32.f16.f16.f32 "
        "{%0,%1,%2,%3}, {%4,%5,%6,%7}, {%8,%9}, {%0,%1,%2,%3};"
        : "+f"(c[0]), "+f"(c[1]), "+f"(c[2]), "+f"(c[3])
        : "r"(a[0]), "r"(a[1]), "r"(a[2]), "r"(a[3]), "r"(b0), "r"(b1));
}

__device__ __forceinline__ void ldsm_x4(uint32_t& d0, uint32_t& d1,
                                        uint32_t& d2, uint32_t& d3, uint32_t a) {
    asm volatile("ldmatrix.sync.aligned.m8n8.x4.shared.b16 {%0,%1,%2,%3}, [%4];"
                 : "=r"(d0), "=r"(d1), "=r"(d2), "=r"(d3) : "r"(a));
}
__device__ __forceinline__ void ldsm_x4_t(uint32_t& d0, uint32_t& d1,
                                          uint32_t& d2, uint32_t& d3, uint32_t a) {
    asm volatile("ldmatrix.sync.aligned.m8n8.x4.trans.shared.b16 {%0,%1,%2,%3}, [%4];"
                 : "=r"(d0), "=r"(d1), "=r"(d2), "=r"(d3) : "r"(a));
}

__device__ __forceinline__ void cp_async16(uint32_t dst, const void* src) {
    asm volatile("cp.async.cg.shared.global [%0], [%1], 16;"
                 :: "r"(dst), "l"(src) : "memory");
}
__device__ __forceinline__ void cp_commit() {
    asm volatile("cp.async.commit_group;" ::: "memory");
}
template <int N>
__device__ __forceinline__ void cp_wait() {
    asm volatile("cp.async.wait_group %0;" :: "n"(N) : "memory");
}

// ---------------------------------------------------------------------------
// Prepass 1: weight transpose -> fp16: WT[z][n][k] = fp16(W[z][k][n])
// ---------------------------------------------------------------------------
struct TransArgs { const float* src[4]; __half* dst; };

__global__ __launch_bounds__(256) void trans4_kernel(TransArgs a)
{
    __shared__ float t[32][33];
    const int z = blockIdx.z;
    const float* W = a.src[z];
    __half* D = a.dst + (size_t)z * NDIM * KDIM;

    int x = blockIdx.x * 32 + threadIdx.x;
    int y0 = blockIdx.y * 32;
#pragma unroll
    for (int j = 0; j < 32; j += 8)
        t[threadIdx.y + j][threadIdx.x] = W[(size_t)(y0 + threadIdx.y + j) * 1024 + x];
    __syncthreads();
    int x2 = blockIdx.y * 32 + threadIdx.x;
    int y2 = blockIdx.x * 32;
#pragma unroll
    for (int j = 0; j < 32; j += 8)
        D[(size_t)(y2 + threadIdx.y + j) * 1024 + x2] =
            __float2half_rn(t[threadIdx.x][threadIdx.y + j]);
}

// ---------------------------------------------------------------------------
// Prepass 2: fp32 -> fp16 convert of input activations
// ---------------------------------------------------------------------------
struct CvtArgs { const float* src[3]; __half* dst[3]; };

__global__ __launch_bounds__(256) void cvt_kernel(CvtArgs a)
{
    const int z = blockIdx.z;
    const float* X = a.src[z];
    __half* H = a.dst[z];
    size_t i = ((size_t)blockIdx.x * 256 + threadIdx.x) * 4;
    if (i >= (size_t)MDIM * NDIM) return;
    float4 v = *(const float4*)(X + i);
    __half2 h01 = __floats2half2_rn(v.x, v.y);
    __half2 h23 = __floats2half2_rn(v.z, v.w);
    uint2 pk;
    pk.x = *(uint32_t*)&h01;
    pk.y = *(uint32_t*)&h23;
    *(uint2*)(H + i) = pk;
}

// ---------------------------------------------------------------------------
// Single-pass fp16 mma.sync GEMM (verified round 11): C = A @ B^T.
// CTA 128x128, 256 thr, 8 warps (2M x 4N), BK=32, 3-stage pipeline, 2 CTAs/SM.
// ---------------------------------------------------------------------------
#define WROW 20
#define TILEW (128 * WROW)
#define STW (2 * TILEW)                  // A, B
#define NBUF 3
#define GSMEM (NBUF * STW * 4)           // 61440 bytes

struct GemmArgsH {
    const __half *A[3], *B[3];
    float* C[3];
    __half* D1[3];
    int mode[3];
};

__device__ __forceinline__ void gemm_load_stage(
    const __half* __restrict__ A, const __half* __restrict__ B,
    int s, uint32_t sbase, int tid)
{
#pragma unroll
    for (int i = 0; i < 2; i++) {
        const int idx = tid + i * 256;      // 0..511
        const int r = idx >> 2;             // 0..127
        const int c = idx & 3;              // 0..3 (16B chunks)
        const uint32_t doff = (uint32_t)(r * WROW + c * 4) * 4;
        const size_t goff = (size_t)r * KDIM + s * 32 + c * 8;
        cp_async16(sbase + doff,             A + goff);
        cp_async16(sbase + TILEW * 4 + doff, B + goff);
    }
    cp_commit();
}

__global__ void __launch_bounds__(256, 2)
gemm_f16_kernel(GemmArgsH args)
{
    extern __shared__ uint32_t sw[];
    const int tid = threadIdx.x;
    const int lane = tid & 31;
    const int wid = tid >> 5;          // 0..7
    const int wm = wid >> 2;           // 0..1 -> M offset wm*64
    const int wn = wid & 3;            // 0..3 -> N offset wn*32
    const int r0 = lane >> 2;
    const int c0 = lane & 3;
    const int z = blockIdx.z;

    const size_t aoff = (size_t)blockIdx.y * 128 * KDIM;
    const size_t boff = (size_t)blockIdx.x * 128 * KDIM;
    const __half* A = args.A[z] + aoff;
    const __half* Bw = args.B[z] + boff;

    const uint32_t sbase = smem_u32(sw);

    float acc[4][4][4];
#pragma unroll
    for (int i = 0; i < 4; i++)
#pragma unroll
        for (int j = 0; j < 4; j++)
#pragma unroll
            for (int k = 0; k < 4; k++) acc[i][j][k] = 0.0f;

    gemm_load_stage(A, Bw, 0, sbase + 0 * STW * 4, tid);
    gemm_load_stage(A, Bw, 1, sbase + 1 * STW * 4, tid);

    const int NST = KDIM / 32;
    for (int s = 0; s < NST; s++) {
        if (s + 1 < NST) cp_wait<1>();
        else             cp_wait<0>();
        __syncthreads();
        if (s + 2 < NST)
            gemm_load_stage(A, Bw, s + 2, sbase + ((s + 2) % NBUF) * STW * 4, tid);
        const uint32_t* St = sw + (s % NBUF) * STW;

#pragma unroll
        for (int ks = 0; ks < 2; ks++) {
            uint32_t af[4][4], bf[4][2];
#pragma unroll
            for (int nt = 0; nt < 4; nt++) {
                const int n = wn * 32 + nt * 8 + r0;
                const int nb = TILEW + n * WROW + ks * 8 + c0;
                bf[nt][0] = St[nb];
                bf[nt][1] = St[nb + 4];
            }
#pragma unroll
            for (int mt = 0; mt < 4; mt++) {
                const int row = wm * 64 + mt * 16 + r0;
                const int base = row * WROW + ks * 8 + c0;
                af[mt][0] = St[base];
                af[mt][1] = St[base + 8 * WROW];
                af[mt][2] = St[base + 4];
                af[mt][3] = St[base + 8 * WROW + 4];
            }
#pragma unroll
            for (int mt = 0; mt < 4; mt++)
#pragma unroll
                for (int nt = 0; nt < 4; nt++)
                    mma_f16(acc[mt][nt], af[mt], bf[nt][0], bf[nt][1]);
        }
    }

    const int mode = args.mode[z];
    const size_t crow0 = (size_t)blockIdx.y * 128 + wm * 64;
    const size_t ccol0 = (size_t)blockIdx.x * 128 + wn * 32;
#pragma unroll
    for (int mt = 0; mt < 4; mt++) {
#pragma unroll
        for (int nt = 0; nt < 4; nt++) {
            const size_t row = crow0 + mt * 16 + r0;
            const size_t col = ccol0 + nt * 8 + c0 * 2;
            float* c = acc[mt][nt];
            if (mode == 0) {
                float* C = args.C[z];
                *(float2*)(C + row * NDIM + col)       = make_float2(c[0], c[1]);
                *(float2*)(C + (row + 8) * NDIM + col) = make_float2(c[2], c[3]);
            } else {
                __half* D1 = args.D1[z];
                __half2 h01 = __floats2half2_rn(c[0], c[1]);
                __half2 h23 = __floats2half2_rn(c[2], c[3]);
                *(__half2*)(D1 + row * NDIM + col)       = h01;
                *(__half2*)(D1 + (row + 8) * NDIM + col) = h23;
            }
        }
    }
}

// ---------------------------------------------------------------------------
// fp16 tensor-core attention, P in registers, 32 query rows per warp.
// CTA = 256 queries of one (b,h); 8 warps x 32 rows (2 m-tiles of 16).
// K/V fragments amortized over 2x the MMA work -> smem reads per query halved.
// 3-stage K/V cp.async pipeline. 1 CTA/SM (regs ~190).
// ---------------------------------------------------------------------------
#define HKS 72
#define KVSTG (2 * 64 * HKS)                 // halfs per stage (K tile + V tile)
#define NKBUF 3
#define HSM_BYTES (NKBUF * KVSTG * 2)        // 55296 B

__device__ __forceinline__ void attn_load_kv16(
    const __half* __restrict__ Kg, const __half* __restrict__ Vg,
    int t, uint32_t stg_base, int tid)
{
    const uint32_t kb = stg_base;
    const uint32_t vb = stg_base + 64 * HKS * 2;
#pragma unroll
    for (int i = 0; i < 2; i++) {
        int idx = tid + i * 256;
        int r = idx >> 3;
        int c = idx & 7;
        const uint32_t doff = (uint32_t)(r * HKS + c * 8) * 2;
        cp_async16(kb + doff, Kg + (size_t)(t * 64 + r) * 64 + c * 8);
        cp_async16(vb + doff, Vg + (size_t)(t * 64 + r) * 64 + c * 8);
    }
    cp_commit();
}

__global__ void __launch_bounds__(256, 1)
attn_fp16_kernel(const __half* __restrict__ Qh, const __half* __restrict__ Kh,
                 const __half* __restrict__ Vh, __half* __restrict__ Oh)
{
    extern __shared__ __half hsm[];
    const int tid = threadIdx.x;
    const int lane = tid & 31;
    const int w = tid >> 5;
    const int r0 = lane >> 2;
    const int c0 = lane & 3;
    const int h = blockIdx.y;
    const int b = blockIdx.z;
    const int qbase = blockIdx.x * 256;
    const size_t off = ((size_t)b * 2048 + h * 128) * 1024;

    const __half* Qg = Qh + off;
    const __half* Kg = Kh + off;
    const __half* Vg = Vh + off;
    const uint32_t sb = smem_u32(hsm);

    // Q fragments: 2 m-tiles of 16 rows each
    uint32_t qf[2][4][4];
    const int row0 = qbase + w * 32 + r0;
#pragma unroll
    for (int mt = 0; mt < 2; mt++)
#pragma unroll
        for (int kg = 0; kg < 4; kg++)
#pragma unroll
            for (int q = 0; q < 4; q++) {
                int row = row0 + mt * 16 + (q & 1) * 8;
                int col = kg * 16 + (q >> 1) * 8 + 2 * c0;
                qf[mt][kg][q] = *(const uint32_t*)(Qg + (size_t)row * 64 + col);
            }

    float oacc[2][8][4];
#pragma unroll
    for (int mt = 0; mt < 2; mt++)
#pragma unroll
        for (int nt = 0; nt < 8; nt++)
#pragma unroll
            for (int j = 0; j < 4; j++) oacc[mt][nt][j] = 0.0f;
    float ls[2][2];
    ls[0][0] = ls[0][1] = ls[1][0] = ls[1][1] = 0.f;

    // 3-stage prologue
    attn_load_kv16(Kg, Vg, 0, sb + 0 * KVSTG * 2, tid);
    attn_load_kv16(Kg, Vg, 1, sb + 1 * KVSTG * 2, tid);

    for (int t = 0; t < 32; t++) {
        if (t + 1 < 32) cp_wait<1>();
        else            cp_wait<0>();
        __syncthreads();
        if (t + 2 < 32)
            attn_load_kv16(Kg, Vg, t + 2, sb + ((t + 2) % NKBUF) * KVSTG * 2, tid);

        const uint32_t kbase = sb + (uint32_t)((t % NKBUF) * KVSTG) * 2;
        const uint32_t vbase = kbase + 64 * HKS * 2;

        // ---- S = Q @ K^T ----
        float sacc[2][8][4];
#pragma unroll
        for (int mt = 0; mt < 2; mt++)
#pragma unroll
            for (int nt = 0; nt < 8; nt++)
#pragma unroll
                for (int j = 0; j < 4; j++) sacc[mt][nt][j] = 0.0f;

#pragma unroll
        for (int nt = 0; nt < 8; nt++) {
            uint32_t bk[4][2];
#pragma unroll
            for (int p = 0; p < 2; p++) {
                uint32_t a = kbase +
                    (uint32_t)((nt * 8 + (lane & 7)) * HKS + p * 32 + (lane >> 3) * 8) * 2;
                ldsm_x4(bk[2 * p][0], bk[2 * p][1], bk[2 * p + 1][0], bk[2 * p + 1][1], a);
            }
#pragma unroll
            for (int mt = 0; mt < 2; mt++)
#pragma unroll
                for (int kg = 0; kg < 4; kg++)
                    mma_f16(sacc[mt][nt], qf[mt][kg], bk[kg][0], bk[kg][1]);
        }

        // ---- P = exp(S/8): pack QK C-frags directly into PV A-frags ----
        uint32_t pfrag[2][4][4];
#pragma unroll
        for (int mt = 0; mt < 2; mt++)
#pragma unroll
            for (int nt = 0; nt < 8; nt++) {
                float p0 = __expf(sacc[mt][nt][0] * 0.125f);
                float p1 = __expf(sacc[mt][nt][1] * 0.125f);
                float p2 = __expf(sacc[mt][nt][2] * 0.125f);
                float p3 = __expf(sacc[mt][nt][3] * 0.125f);
                ls[mt][0] += p0 + p1;
                ls[mt][1] += p2 + p3;
                __half2 h01 = __floats2half2_rn(p0, p1);
                __half2 h23 = __floats2half2_rn(p2, p3);
                pfrag[mt][nt >> 1][(nt & 1) * 2 + 0] = *(uint32_t*)&h01;
                pfrag[mt][nt >> 1][(nt & 1) * 2 + 1] = *(uint32_t*)&h23;
            }

        // ---- O += P @ V ----
#pragma unroll
        for (int kg = 0; kg < 4; kg++) {
#pragma unroll
            for (int p = 0; p < 4; p++) {
                uint32_t bv0, bv1, bv2, bv3;
                uint32_t a = vbase +
                    (uint32_t)((kg * 16 + ((lane >> 3) & 1) * 8 + (lane & 7)) * HKS +
                               p * 16 + (lane >> 4) * 8) * 2;
                ldsm_x4_t(bv0, bv1, bv2, bv3, a);
#pragma unroll
                for (int mt = 0; mt < 2; mt++) {
                    mma_f16(oacc[mt][2 * p],     pfrag[mt][kg], bv0, bv1);
                    mma_f16(oacc[mt][2 * p + 1], pfrag[mt][kg], bv2, bv3);
                }
            }
        }
    }

#pragma unroll
    for (int mt = 0; mt < 2; mt++) {
        ls[mt][0] += __shfl_xor_sync(0xffffffffu, ls[mt][0], 1);
        ls[mt][0] += __shfl_xor_sync(0xffffffffu, ls[mt][0], 2);
        ls[mt][1] += __shfl_xor_sync(0xffffffffu, ls[mt][1], 1);
        ls[mt][1] += __shfl_xor_sync(0xffffffffu, ls[mt][1], 2);
    }

#pragma unroll
    for (int mt = 0; mt < 2; mt++) {
        const float inv0 = 1.0f / ls[mt][0];
        const float inv1 = 1.0f / ls[mt][1];
        const int rbase = row0 + mt * 16;
#pragma unroll
        for (int nt = 0; nt < 8; nt++) {
            const int col = h * 64 + nt * 8 + 2 * c0;
            __half2 hh01 = __floats2half2_rn(oacc[mt][nt][0] * inv0,
                                             oacc[mt][nt][1] * inv0);
            __half2 hh23 = __floats2half2_rn(oacc[mt][nt][2] * inv1,
                                             oacc[mt][nt][3] * inv1);
            *(__half2*)(Oh + ((size_t)(b * 2048 + rbase)) * 1024 + col)     = hh01;
            *(__half2*)(Oh + ((size_t)(b * 2048 + rbase + 8)) * 1024 + col) = hh23;
        }
    }
}

// ---------------------------------------------------------------------------
// Launch
// ---------------------------------------------------------------------------
extern "C" void kernel_launch(void* const* d_in, const int* in_sizes, int n_in,
                              void* d_out, int out_size)
{
    const float* Q  = (const float*)d_in[0];
    const float* K  = (const float*)d_in[1];
    const float* V  = (const float*)d_in[2];
    const float* WQ = (const float*)d_in[3];
    const float* WK = (const float*)d_in[4];
    const float* WV = (const float*)d_in[5];
    const float* Wf = (const float*)d_in[6];
    float* out = (float*)d_out;

    __half *X, *WT, *Qh, *Kh, *Vh;
    cudaGetSymbolAddress((void**)&X,  g_X);
    cudaGetSymbolAddress((void**)&WT, g_WT);
    cudaGetSymbolAddress((void**)&Qh, g_Qh);
    cudaGetSymbolAddress((void**)&Kh, g_Kh);
    cudaGetSymbolAddress((void**)&Vh, g_Vh);

    cudaFuncSetAttribute(gemm_f16_kernel,
                         cudaFuncAttributeMaxDynamicSharedMemorySize, GSMEM);
    cudaFuncSetAttribute(attn_fp16_kernel,
                         cudaFuncAttributeMaxDynamicSharedMemorySize, HSM_BYTES);

    const size_t NEL = (size_t)MDIM * NDIM;

    // 1) weights: transpose -> fp16
    TransArgs t;
    t.src[0] = WQ; t.src[1] = WK; t.src[2] = WV; t.src[3] = Wf;
    t.dst = WT;
    trans4_kernel<<<dim3(32, 32, 4), dim3(32, 8)>>>(t);

    // 2) input activations -> fp16
    CvtArgs cv;
    cv.src[0] = Q; cv.src[1] = K; cv.src[2] = V;
    for (int i = 0; i < 3; i++) cv.dst[i] = X + i * NEL;
    cvt_kernel<<<dim3((unsigned)(NEL / 4 / 256), 1, 3), 256>>>(cv);

    // 3) Q/K/V projections -> fp16
    GemmArgsH g1;
    for (int i = 0; i < 3; i++) {
        g1.A[i] = X + i * NEL;
        g1.B[i] = WT + (size_t)i * NDIM * KDIM;
        g1.C[i] = nullptr;
        g1.mode[i] = 2;
    }
    g1.D1[0] = Qh; g1.D1[1] = Kh; g1.D1[2] = Vh;
    gemm_f16_kernel<<<dim3(NDIM / 128, MDIM / 128, 3), 256, GSMEM>>>(g1);

    // 4) attention -> ctx fp16 into slot 0  (256 queries per CTA)
    attn_fp16_kernel<<<dim3(8, 16, 4), 256, HSM_BYTES>>>(Qh, Kh, Vh, X);

    // 5) output projection (f32 out)
    GemmArgsH g2;
    for (int i = 0; i < 3; i++) {
        g2.A[i] = X;
        g2.B[i] = WT + (size_t)3 * NDIM * KDIM;
        g2.C[i] = out;
        g2.D1[i] = nullptr;
        g2.mode[i] = 0;
    }
    gemm_f16_kernel<<<dim3(NDIM / 128, MDIM / 128, 1), 256, GSMEM>>>(g2);
}

// round 13
// speedup vs baseline: 1.0766x; 1.0766x over previous
#include <cuda_runtime.h>
#include <cuda_fp16.h>
#include <cstdint>

// Shapes (fixed): B=4, S=2048, D=1024, H=16, dk=64.
#define MDIM 8192
#define NDIM 1024
#define KDIM 1024

// ---------------------------------------------------------------------------
// Device scratch (allocation-free per harness rules)
// ---------------------------------------------------------------------------
__device__ __half g_X[3][MDIM * NDIM];    // fp16 activations (slot 0 reused for ctx)
__device__ __half g_WT[4][NDIM * KDIM];   // transposed weights, fp16
__device__ __half g_Qh[MDIM * NDIM];      // fp16 projections for attention
__device__ __half g_Kh[MDIM * NDIM];
__device__ __half g_Vh[MDIM * NDIM];

// ---------------------------------------------------------------------------
// Helpers
// ---------------------------------------------------------------------------
__device__ __forceinline__ uint32_t smem_u32(const void* p) {
    uint32_t a;
    asm("{ .reg .u64 t; cvta.to.shared.u64 t, %1; cvt.u32.u64 %0, t; }"
        : "=r"(a) : "l"(p));
    return a;
}

__device__ __forceinline__ void mma_f16(float* c, const uint32_t* a,
                                        uint32_t b0, uint32_t b1) {
    asm volatile(
        "mma.sync.aligned.m16n8k16.row.col.f32.f16.f16.f32 "
        "{%0,%1,%2,%3}, {%4,%5,%6,%7}, {%8,%9}, {%0,%1,%2,%3};"
        : "+f"(c[0]), "+f"(c[1]), "+f"(c[2]), "+f"(c[3])
        : "r"(a[0]), "r"(a[1]), "r"(a[2]), "r"(a[3]), "r"(b0), "r"(b1));
}

__device__ __forceinline__ void ldsm_x4(uint32_t& d0, uint32_t& d1,
                                        uint32_t& d2, uint32_t& d3, uint32_t a) {
    asm volatile("ldmatrix.sync.aligned.m8n8.x4.shared.b16 {%0,%1,%2,%3}, [%4];"
                 : "=r"(d0), "=r"(d1), "=r"(d2), "=r"(d3) : "r"(a));
}
__device__ __forceinline__ void ldsm_x4_t(uint32_t& d0, uint32_t& d1,
                                          uint32_t& d2, uint32_t& d3, uint32_t a) {
    asm volatile("ldmatrix.sync.aligned.m8n8.x4.trans.shared.b16 {%0,%1,%2,%3}, [%4];"
                 : "=r"(d0), "=r"(d1), "=r"(d2), "=r"(d3) : "r"(a));
}

__device__ __forceinline__ void cp_async16(uint32_t dst, const void* src) {
    asm volatile("cp.async.cg.shared.global [%0], [%1], 16;"
                 :: "r"(dst), "l"(src) : "memory");
}
__device__ __forceinline__ void cp_commit() {
    asm volatile("cp.async.commit_group;" ::: "memory");
}
template <int N>
__device__ __forceinline__ void cp_wait() {
    asm volatile("cp.async.wait_group %0;" :: "n"(N) : "memory");
}

// ---------------------------------------------------------------------------
// Prepass 1: weight transpose -> fp16: WT[z][n][k] = fp16(W[z][k][n])
// ---------------------------------------------------------------------------
struct TransArgs { const float* src[4]; __half* dst; };

__global__ __launch_bounds__(256) void trans4_kernel(TransArgs a)
{
    __shared__ float t[32][33];
    const int z = blockIdx.z;
    const float* W = a.src[z];
    __half* D = a.dst + (size_t)z * NDIM * KDIM;

    int x = blockIdx.x * 32 + threadIdx.x;
    int y0 = blockIdx.y * 32;
#pragma unroll
    for (int j = 0; j < 32; j += 8)
        t[threadIdx.y + j][threadIdx.x] = W[(size_t)(y0 + threadIdx.y + j) * 1024 + x];
    __syncthreads();
    int x2 = blockIdx.y * 32 + threadIdx.x;
    int y2 = blockIdx.x * 32;
#pragma unroll
    for (int j = 0; j < 32; j += 8)
        D[(size_t)(y2 + threadIdx.y + j) * 1024 + x2] =
            __float2half_rn(t[threadIdx.x][threadIdx.y + j]);
}

// ---------------------------------------------------------------------------
// Prepass 2: fp32 -> fp16 convert of input activations
// ---------------------------------------------------------------------------
struct CvtArgs { const float* src[3]; __half* dst[3]; };

__global__ __launch_bounds__(256) void cvt_kernel(CvtArgs a)
{
    const int z = blockIdx.z;
    const float* X = a.src[z];
    __half* H = a.dst[z];
    size_t i = ((size_t)blockIdx.x * 256 + threadIdx.x) * 4;
    if (i >= (size_t)MDIM * NDIM) return;
    float4 v = *(const float4*)(X + i);
    __half2 h01 = __floats2half2_rn(v.x, v.y);
    __half2 h23 = __floats2half2_rn(v.z, v.w);
    uint2 pk;
    pk.x = *(uint32_t*)&h01;
    pk.y = *(uint32_t*)&h23;
    *(uint2*)(H + i) = pk;
}

// ---------------------------------------------------------------------------
// Single-pass fp16 mma.sync GEMM: C = A @ B^T, BK=64, 3-stage pipeline,
// CTA 128x128, 256 thr, 8 warps (2M x 4N), 2 CTAs/SM.
// Epilogue modes: 0: C f32;  2: D1 fp16
// ---------------------------------------------------------------------------
#define WROW 36                           // words per smem row (64 halfs + pad)
#define TILEW (128 * WROW)                // 4608 words per tile
#define STW (2 * TILEW)                   // A, B = 9216 words
#define NBUF 3
#define GSMEM (NBUF * STW * 4)            // 110592 bytes

struct GemmArgsH {
    const __half *A[3], *B[3];
    float* C[3];
    __half* D1[3];
    int mode[3];
};

__device__ __forceinline__ void gemm_load_stage(
    const __half* __restrict__ A, const __half* __restrict__ B,
    int s, uint32_t sbase, int tid)
{
#pragma unroll
    for (int i = 0; i < 4; i++) {
        const int idx = tid + i * 256;      // 0..1023
        const int r = idx >> 3;             // 0..127
        const int c = idx & 7;              // 0..7 (16B chunks)
        const uint32_t doff = (uint32_t)(r * WROW + c * 4) * 4;
        const size_t goff = (size_t)r * KDIM + s * 64 + c * 8;
        cp_async16(sbase + doff,             A + goff);
        cp_async16(sbase + TILEW * 4 + doff, B + goff);
    }
    cp_commit();
}

__global__ void __launch_bounds__(256, 2)
gemm_f16_kernel(GemmArgsH args)
{
    extern __shared__ uint32_t sw[];
    const int tid = threadIdx.x;
    const int lane = tid & 31;
    const int wid = tid >> 5;          // 0..7
    const int wm = wid >> 2;           // 0..1 -> M offset wm*64
    const int wn = wid & 3;            // 0..3 -> N offset wn*32
    const int r0 = lane >> 2;
    const int c0 = lane & 3;
    const int z = blockIdx.z;

    const size_t aoff = (size_t)blockIdx.y * 128 * KDIM;
    const size_t boff = (size_t)blockIdx.x * 128 * KDIM;
    const __half* A = args.A[z] + aoff;
    const __half* Bw = args.B[z] + boff;

    const uint32_t sbase = smem_u32(sw);

    float acc[4][4][4];
#pragma unroll
    for (int i = 0; i < 4; i++)
#pragma unroll
        for (int j = 0; j < 4; j++)
#pragma unroll
            for (int k = 0; k < 4; k++) acc[i][j][k] = 0.0f;

    gemm_load_stage(A, Bw, 0, sbase + 0 * STW * 4, tid);
    gemm_load_stage(A, Bw, 1, sbase + 1 * STW * 4, tid);

    const int NST = KDIM / 64;          // 16
    for (int s = 0; s < NST; s++) {
        if (s + 1 < NST) cp_wait<1>();
        else             cp_wait<0>();
        __syncthreads();
        if (s + 2 < NST)
            gemm_load_stage(A, Bw, s + 2, sbase + ((s + 2) % NBUF) * STW * 4, tid);
        const uint32_t* St = sw + (s % NBUF) * STW;

#pragma unroll
        for (int ks = 0; ks < 4; ks++) {
            uint32_t af[4][4], bf[4][2];
#pragma unroll
            for (int nt = 0; nt < 4; nt++) {
                const int n = wn * 32 + nt * 8 + r0;
                const int nb = TILEW + n * WROW + ks * 8 + c0;
                bf[nt][0] = St[nb];
                bf[nt][1] = St[nb + 4];
            }
#pragma unroll
            for (int mt = 0; mt < 4; mt++) {
                const int row = wm * 64 + mt * 16 + r0;
                const int base = row * WROW + ks * 8 + c0;
                af[mt][0] = St[base];
                af[mt][1] = St[base + 8 * WROW];
                af[mt][2] = St[base + 4];
                af[mt][3] = St[base + 8 * WROW + 4];
            }
#pragma unroll
            for (int mt = 0; mt < 4; mt++)
#pragma unroll
                for (int nt = 0; nt < 4; nt++)
                    mma_f16(acc[mt][nt], af[mt], bf[nt][0], bf[nt][1]);
        }
    }

    const int mode = args.mode[z];
    const size_t crow0 = (size_t)blockIdx.y * 128 + wm * 64;
    const size_t ccol0 = (size_t)blockIdx.x * 128 + wn * 32;
#pragma unroll
    for (int mt = 0; mt < 4; mt++) {
#pragma unroll
        for (int nt = 0; nt < 4; nt++) {
            const size_t row = crow0 + mt * 16 + r0;
            const size_t col = ccol0 + nt * 8 + c0 * 2;
            float* c = acc[mt][nt];
            if (mode == 0) {
                float* C = args.C[z];
                *(float2*)(C + row * NDIM + col)       = make_float2(c[0], c[1]);
                *(float2*)(C + (row + 8) * NDIM + col) = make_float2(c[2], c[3]);
            } else {
                __half* D1 = args.D1[z];
                __half2 h01 = __floats2half2_rn(c[0], c[1]);
                __half2 h23 = __floats2half2_rn(c[2], c[3]);
                *(__half2*)(D1 + row * NDIM + col)       = h01;
                *(__half2*)(D1 + (row + 8) * NDIM + col) = h23;
            }
        }
    }
}

// ---------------------------------------------------------------------------
// fp16 tensor-core attention (R11 tile: 16 query rows/warp, 2 CTAs/SM),
// but with 128-key pipeline stages processed as two 64-key halves.
// 3-stage cp.async pipeline -> one __syncthreads per 128 keys.
// Key processing order identical to R11 -> bit-identical results.
// ---------------------------------------------------------------------------
#define HKS 72
#define KVSTG (2 * 128 * HKS)                // halfs per stage (K + V, 128 keys)
#define NKBUF 3
#define HSM_BYTES (NKBUF * KVSTG * 2)        // 110592 B

__device__ __forceinline__ void attn_load_kv16(
    const __half* __restrict__ Kg, const __half* __restrict__ Vg,
    int t, uint32_t stg_base, int tid)
{
    const uint32_t kb = stg_base;
    const uint32_t vb = stg_base + 128 * HKS * 2;
#pragma unroll
    for (int i = 0; i < 4; i++) {
        int idx = tid + i * 256;            // 0..1023
        int r = idx >> 3;                   // 0..127 (key row in stage)
        int c = idx & 7;                    // 16B chunk
        const uint32_t doff = (uint32_t)(r * HKS + c * 8) * 2;
        cp_async16(kb + doff, Kg + (size_t)(t * 128 + r) * 64 + c * 8);
        cp_async16(vb + doff, Vg + (size_t)(t * 128 + r) * 64 + c * 8);
    }
    cp_commit();
}

__global__ void __launch_bounds__(256, 2)
attn_fp16_kernel(const __half* __restrict__ Qh, const __half* __restrict__ Kh,
                 const __half* __restrict__ Vh, __half* __restrict__ Oh)
{
    extern __shared__ __half hsm[];
    const int tid = threadIdx.x;
    const int lane = tid & 31;
    const int w = tid >> 5;
    const int r0 = lane >> 2;
    const int c0 = lane & 3;
    const int h = blockIdx.y;
    const int b = blockIdx.z;
    const int qbase = blockIdx.x * 128;
    const size_t off = ((size_t)b * 2048 + h * 128) * 1024;

    const __half* Qg = Qh + off;
    const __half* Kg = Kh + off;
    const __half* Vg = Vh + off;
    const uint32_t sb = smem_u32(hsm);

    uint32_t qf[4][4];
    const int row0 = qbase + w * 16 + r0;
#pragma unroll
    for (int kg = 0; kg < 4; kg++)
#pragma unroll
        for (int q = 0; q < 4; q++) {
            int row = row0 + (q & 1) * 8;
            int col = kg * 16 + (q >> 1) * 8 + 2 * c0;
            qf[kg][q] = *(const uint32_t*)(Qg + (size_t)row * 64 + col);
        }

    float oacc[8][4];
#pragma unroll
    for (int nt = 0; nt < 8; nt++)
#pragma unroll
        for (int j = 0; j < 4; j++) oacc[nt][j] = 0.0f;
    float ls0 = 0.f, ls1 = 0.f;

    // 3-stage prologue (stages of 128 keys; 16 stages total)
    attn_load_kv16(Kg, Vg, 0, sb + 0 * KVSTG * 2, tid);
    attn_load_kv16(Kg, Vg, 1, sb + 1 * KVSTG * 2, tid);

    for (int t = 0; t < 16; t++) {
        if (t + 1 < 16) cp_wait<1>();
        else            cp_wait<0>();
        __syncthreads();
        if (t + 2 < 16)
            attn_load_kv16(Kg, Vg, t + 2, sb + ((t + 2) % NKBUF) * KVSTG * 2, tid);

        const uint32_t stg = sb + (uint32_t)((t % NKBUF) * KVSTG) * 2;

        // two 64-key halves, same order as the 64-key pipeline (bit-identical)
#pragma unroll
        for (int half = 0; half < 2; half++) {
            const uint32_t kbase = stg + (uint32_t)(half * 64 * HKS) * 2;
            const uint32_t vbase = stg + (uint32_t)(128 * HKS + half * 64 * HKS) * 2;

            // ---- S = Q @ K^T ----
            float sacc[8][4];
#pragma unroll
            for (int nt = 0; nt < 8; nt++)
#pragma unroll
                for (int j = 0; j < 4; j++) sacc[nt][j] = 0.0f;

#pragma unroll
            for (int nt = 0; nt < 8; nt++) {
                uint32_t bk[4][2];
#pragma unroll
                for (int p = 0; p < 2; p++) {
                    uint32_t a = kbase +
                        (uint32_t)((nt * 8 + (lane & 7)) * HKS + p * 32 + (lane >> 3) * 8) * 2;
                    ldsm_x4(bk[2 * p][0], bk[2 * p][1], bk[2 * p + 1][0], bk[2 * p + 1][1], a);
                }
#pragma unroll
                for (int kg = 0; kg < 4; kg++)
                    mma_f16(sacc[nt], qf[kg], bk[kg][0], bk[kg][1]);
            }

            // ---- P = exp(S/8): pack QK C-frags directly into PV A-frags ----
            uint32_t pfrag[4][4];
#pragma unroll
            for (int nt = 0; nt < 8; nt++) {
                float p0 = __expf(sacc[nt][0] * 0.125f);
                float p1 = __expf(sacc[nt][1] * 0.125f);
                float p2 = __expf(sacc[nt][2] * 0.125f);
                float p3 = __expf(sacc[nt][3] * 0.125f);
                ls0 += p0 + p1;
                ls1 += p2 + p3;
                __half2 h01 = __floats2half2_rn(p0, p1);
                __half2 h23 = __floats2half2_rn(p2, p3);
                pfrag[nt >> 1][(nt & 1) * 2 + 0] = *(uint32_t*)&h01;
                pfrag[nt >> 1][(nt & 1) * 2 + 1] = *(uint32_t*)&h23;
            }

            // ---- O += P @ V ----
#pragma unroll
            for (int kg = 0; kg < 4; kg++) {
#pragma unroll
                for (int p = 0; p < 4; p++) {
                    uint32_t bv0, bv1, bv2, bv3;
                    uint32_t a = vbase +
                        (uint32_t)((kg * 16 + ((lane >> 3) & 1) * 8 + (lane & 7)) * HKS +
                                   p * 16 + (lane >> 4) * 8) * 2;
                    ldsm_x4_t(bv0, bv1, bv2, bv3, a);
                    mma_f16(oacc[2 * p],     pfrag[kg], bv0, bv1);
                    mma_f16(oacc[2 * p + 1], pfrag[kg], bv2, bv3);
                }
            }
        }
    }

    ls0 += __shfl_xor_sync(0xffffffffu, ls0, 1);
    ls0 += __shfl_xor_sync(0xffffffffu, ls0, 2);
    ls1 += __shfl_xor_sync(0xffffffffu, ls1, 1);
    ls1 += __shfl_xor_sync(0xffffffffu, ls1, 2);
    const float inv0 = 1.0f / ls0;
    const float inv1 = 1.0f / ls1;

#pragma unroll
    for (int nt = 0; nt < 8; nt++) {
        const int col = h * 64 + nt * 8 + 2 * c0;
        __half2 hh01 = __floats2half2_rn(oacc[nt][0] * inv0, oacc[nt][1] * inv0);
        __half2 hh23 = __floats2half2_rn(oacc[nt][2] * inv1, oacc[nt][3] * inv1);
        *(__half2*)(Oh + ((size_t)(b * 2048 + row0)) * 1024 + col)     = hh01;
        *(__half2*)(Oh + ((size_t)(b * 2048 + row0 + 8)) * 1024 + col) = hh23;
    }
}

// ---------------------------------------------------------------------------
// Launch
// ---------------------------------------------------------------------------
extern "C" void kernel_launch(void* const* d_in, const int* in_sizes, int n_in,
                              void* d_out, int out_size)
{
    const float* Q  = (const float*)d_in[0];
    const float* K  = (const float*)d_in[1];
    const float* V  = (const float*)d_in[2];
    const float* WQ = (const float*)d_in[3];
    const float* WK = (const float*)d_in[4];
    const float* WV = (const float*)d_in[5];
    const float* Wf = (const float*)d_in[6];
    float* out = (float*)d_out;

    __half *X, *WT, *Qh, *Kh, *Vh;
    cudaGetSymbolAddress((void**)&X,  g_X);
    cudaGetSymbolAddress((void**)&WT, g_WT);
    cudaGetSymbolAddress((void**)&Qh, g_Qh);
    cudaGetSymbolAddress((void**)&Kh, g_Kh);
    cudaGetSymbolAddress((void**)&Vh, g_Vh);

    cudaFuncSetAttribute(gemm_f16_kernel,
                         cudaFuncAttributeMaxDynamicSharedMemorySize, GSMEM);
    cudaFuncSetAttribute(attn_fp16_kernel,
                         cudaFuncAttributeMaxDynamicSharedMemorySize, HSM_BYTES);

    const size_t NEL = (size_t)MDIM * NDIM;

    // 1) weights: transpose -> fp16
    TransArgs t;
    t.src[0] = WQ; t.src[1] = WK; t.src[2] = WV; t.src[3] = Wf;
    t.dst = WT;
    trans4_kernel<<<dim3(32, 32, 4), dim3(32, 8)>>>(t);

    // 2) input activations -> fp16
    CvtArgs cv;
    cv.src[0] = Q; cv.src[1] = K; cv.src[2] = V;
    for (int i = 0; i < 3; i++) cv.dst[i] = X + i * NEL;
    cvt_kernel<<<dim3((unsigned)(NEL / 4 / 256), 1, 3), 256>>>(cv);

    // 3) Q/K/V projections -> fp16
    GemmArgsH g1;
    for (int i = 0; i < 3; i++) {
        g1.A[i] = X + i * NEL;
        g1.B[i] = WT + (size_t)i * NDIM * KDIM;
        g1.C[i] = nullptr;
        g1.mode[i] = 2;
    }
    g1.D1[0] = Qh; g1.D1[1] = Kh; g1.D1[2] = Vh;
    gemm_f16_kernel<<<dim3(NDIM / 128, MDIM / 128, 3), 256, GSMEM>>>(g1);

    // 4) attention -> ctx fp16 into slot 0  (128 queries per CTA)
    attn_fp16_kernel<<<dim3(16, 16, 4), 256, HSM_BYTES>>>(Qh, Kh, Vh, X);

    // 5) output projection (f32 out)
    GemmArgsH g2;
    for (int i = 0; i < 3; i++) {
        g2.A[i] = X;
        g2.B[i] = WT + (size_t)3 * NDIM * KDIM;
        g2.C[i] = out;
        g2.D1[i] = nullptr;
        g2.mode[i] = 0;
    }
    gemm_f16_kernel<<<dim3(NDIM / 128, MDIM / 128, 1), 256, GSMEM>>>(g2);
}

// round 14
// speedup vs baseline: 1.1472x; 1.0655x over previous
#include <cuda_runtime.h>
#include <cuda_fp16.h>
#include <cstdint>

// Shapes (fixed): B=4, S=2048, D=1024, H=16, dk=64.
#define MDIM 8192
#define NDIM 1024
#define KDIM 1024

// ---------------------------------------------------------------------------
// Device scratch (allocation-free per harness rules)
// ---------------------------------------------------------------------------
__device__ __half g_X[3][MDIM * NDIM];    // fp16 activations (slot 0 reused for ctx)
__device__ __half g_WT[4][NDIM * KDIM];   // transposed weights, fp16
__device__ __half g_Qh[MDIM * NDIM];      // fp16 projections for attention
__device__ __half g_Kh[MDIM * NDIM];
__device__ __half g_Vh[MDIM * NDIM];

// 0.125 * log2(e): folded into Q so attention uses bare ex2.approx
#define QSCALE 0.18033688011112042f

// ---------------------------------------------------------------------------
// Helpers
// ---------------------------------------------------------------------------
__device__ __forceinline__ uint32_t smem_u32(const void* p) {
    uint32_t a;
    asm("{ .reg .u64 t; cvta.to.shared.u64 t, %1; cvt.u32.u64 %0, t; }"
        : "=r"(a) : "l"(p));
    return a;
}

__device__ __forceinline__ float ex2f(float x) {
    float y;
    asm("ex2.approx.f32 %0, %1;" : "=f"(y) : "f"(x));
    return y;
}

__device__ __forceinline__ void mma_f16(float* c, const uint32_t* a,
                                        uint32_t b0, uint32_t b1) {
    asm volatile(
        "mma.sync.aligned.m16n8k16.row.col.f32.f16.f16.f32 "
        "{%0,%1,%2,%3}, {%4,%5,%6,%7}, {%8,%9}, {%0,%1,%2,%3};"
        : "+f"(c[0]), "+f"(c[1]), "+f"(c[2]), "+f"(c[3])
        : "r"(a[0]), "r"(a[1]), "r"(a[2]), "r"(a[3]), "r"(b0), "r"(b1));
}

__device__ __forceinline__ void ldsm_x4(uint32_t& d0, uint32_t& d1,
                                        uint32_t& d2, uint32_t& d3, uint32_t a) {
    asm volatile("ldmatrix.sync.aligned.m8n8.x4.shared.b16 {%0,%1,%2,%3}, [%4];"
                 : "=r"(d0), "=r"(d1), "=r"(d2), "=r"(d3) : "r"(a));
}
__device__ __forceinline__ void ldsm_x4_t(uint32_t& d0, uint32_t& d1,
                                          uint32_t& d2, uint32_t& d3, uint32_t a) {
    asm volatile("ldmatrix.sync.aligned.m8n8.x4.trans.shared.b16 {%0,%1,%2,%3}, [%4];"
                 : "=r"(d0), "=r"(d1), "=r"(d2), "=r"(d3) : "r"(a));
}

__device__ __forceinline__ void cp_async16(uint32_t dst, const void* src) {
    asm volatile("cp.async.cg.shared.global [%0], [%1], 16;"
                 :: "r"(dst), "l"(src) : "memory");
}
__device__ __forceinline__ void cp_commit() {
    asm volatile("cp.async.commit_group;" ::: "memory");
}
template <int N>
__device__ __forceinline__ void cp_wait() {
    asm volatile("cp.async.wait_group %0;" :: "n"(N) : "memory");
}

// ---------------------------------------------------------------------------
// Merged prepass: z<4 -> weight transpose to fp16; z>=4 -> activation convert.
// ---------------------------------------------------------------------------
struct PrepArgs {
    const float* w[4];
    __half* wt;
    const float* x[3];
    __half* xd[3];
};

__global__ __launch_bounds__(256) void prep_kernel(PrepArgs a)
{
    const int z = blockIdx.z;
    if (z < 4) {
        __shared__ float t[32][33];
        const float* W = a.w[z];
        __half* D = a.wt + (size_t)z * NDIM * KDIM;

        int x = blockIdx.x * 32 + threadIdx.x;
        int y0 = blockIdx.y * 32;
#pragma unroll
        for (int j = 0; j < 32; j += 8)
            t[threadIdx.y + j][threadIdx.x] =
                W[(size_t)(y0 + threadIdx.y + j) * 1024 + x];
        __syncthreads();
        int x2 = blockIdx.y * 32 + threadIdx.x;
        int y2 = blockIdx.x * 32;
#pragma unroll
        for (int j = 0; j < 32; j += 8)
            D[(size_t)(y2 + threadIdx.y + j) * 1024 + x2] =
                __float2half_rn(t[threadIdx.x][threadIdx.y + j]);
    } else {
        const float* X = a.x[z - 4];
        __half* H = a.xd[z - 4];
        const int tid = threadIdx.y * 32 + threadIdx.x;
        const size_t blk = (size_t)blockIdx.y * 32 + blockIdx.x;   // 0..1023
        // 8.4M floats / 4 per float4 / 1024 blocks / 256 threads = 8 iters
        size_t base = (blk * 256 + tid) * 4;
        const size_t stride = (size_t)1024 * 256 * 4;
#pragma unroll
        for (int it = 0; it < 8; it++) {
            size_t i = base + (size_t)it * stride;
            float4 v = *(const float4*)(X + i);
            __half2 h01 = __floats2half2_rn(v.x, v.y);
            __half2 h23 = __floats2half2_rn(v.z, v.w);
            uint2 pk;
            pk.x = *(uint32_t*)&h01;
            pk.y = *(uint32_t*)&h23;
            *(uint2*)(H + i) = pk;
        }
    }
}

// ---------------------------------------------------------------------------
// Single-pass fp16 mma.sync GEMM: C = A @ B^T, BK=64, 3-stage pipeline,
// CTA 128x128, 256 thr, 8 warps (2M x 4N), 2 CTAs/SM.
// Epilogue modes: 0: C f32;  2: D1 fp16 (scaled by args.scale[z])
// ---------------------------------------------------------------------------
#define WROW 36
#define TILEW (128 * WROW)
#define STW (2 * TILEW)
#define NBUF 3
#define GSMEM (NBUF * STW * 4)            // 110592 bytes

struct GemmArgsH {
    const __half *A[3], *B[3];
    float* C[3];
    __half* D1[3];
    float scale[3];
    int mode[3];
};

__device__ __forceinline__ void gemm_load_stage(
    const __half* __restrict__ A, const __half* __restrict__ B,
    int s, uint32_t sbase, int tid)
{
#pragma unroll
    for (int i = 0; i < 4; i++) {
        const int idx = tid + i * 256;
        const int r = idx >> 3;
        const int c = idx & 7;
        const uint32_t doff = (uint32_t)(r * WROW + c * 4) * 4;
        const size_t goff = (size_t)r * KDIM + s * 64 + c * 8;
        cp_async16(sbase + doff,             A + goff);
        cp_async16(sbase + TILEW * 4 + doff, B + goff);
    }
    cp_commit();
}

__global__ void __launch_bounds__(256, 2)
gemm_f16_kernel(GemmArgsH args)
{
    extern __shared__ uint32_t sw[];
    const int tid = threadIdx.x;
    const int lane = tid & 31;
    const int wid = tid >> 5;
    const int wm = wid >> 2;
    const int wn = wid & 3;
    const int r0 = lane >> 2;
    const int c0 = lane & 3;
    const int z = blockIdx.z;

    const size_t aoff = (size_t)blockIdx.y * 128 * KDIM;
    const size_t boff = (size_t)blockIdx.x * 128 * KDIM;
    const __half* A = args.A[z] + aoff;
    const __half* Bw = args.B[z] + boff;

    const uint32_t sbase = smem_u32(sw);

    float acc[4][4][4];
#pragma unroll
    for (int i = 0; i < 4; i++)
#pragma unroll
        for (int j = 0; j < 4; j++)
#pragma unroll
            for (int k = 0; k < 4; k++) acc[i][j][k] = 0.0f;

    gemm_load_stage(A, Bw, 0, sbase + 0 * STW * 4, tid);
    gemm_load_stage(A, Bw, 1, sbase + 1 * STW * 4, tid);

    const int NST = KDIM / 64;
    for (int s = 0; s < NST; s++) {
        if (s + 1 < NST) cp_wait<1>();
        else             cp_wait<0>();
        __syncthreads();
        if (s + 2 < NST)
            gemm_load_stage(A, Bw, s + 2, sbase + ((s + 2) % NBUF) * STW * 4, tid);
        const uint32_t* St = sw + (s % NBUF) * STW;

#pragma unroll
        for (int ks = 0; ks < 4; ks++) {
            uint32_t af[4][4], bf[4][2];
#pragma unroll
            for (int nt = 0; nt < 4; nt++) {
                const int n = wn * 32 + nt * 8 + r0;
                const int nb = TILEW + n * WROW + ks * 8 + c0;
                bf[nt][0] = St[nb];
                bf[nt][1] = St[nb + 4];
            }
#pragma unroll
            for (int mt = 0; mt < 4; mt++) {
                const int row = wm * 64 + mt * 16 + r0;
                const int base = row * WROW + ks * 8 + c0;
                af[mt][0] = St[base];
                af[mt][1] = St[base + 8 * WROW];
                af[mt][2] = St[base + 4];
                af[mt][3] = St[base + 8 * WROW + 4];
            }
#pragma unroll
            for (int mt = 0; mt < 4; mt++)
#pragma unroll
                for (int nt = 0; nt < 4; nt++)
                    mma_f16(acc[mt][nt], af[mt], bf[nt][0], bf[nt][1]);
        }
    }

    const int mode = args.mode[z];
    const float scl = args.scale[z];
    const size_t crow0 = (size_t)blockIdx.y * 128 + wm * 64;
    const size_t ccol0 = (size_t)blockIdx.x * 128 + wn * 32;
#pragma unroll
    for (int mt = 0; mt < 4; mt++) {
#pragma unroll
        for (int nt = 0; nt < 4; nt++) {
            const size_t row = crow0 + mt * 16 + r0;
            const size_t col = ccol0 + nt * 8 + c0 * 2;
            float* c = acc[mt][nt];
            if (mode == 0) {
                float* C = args.C[z];
                *(float2*)(C + row * NDIM + col)       = make_float2(c[0], c[1]);
                *(float2*)(C + (row + 8) * NDIM + col) = make_float2(c[2], c[3]);
            } else {
                __half* D1 = args.D1[z];
                __half2 h01 = __floats2half2_rn(c[0] * scl, c[1] * scl);
                __half2 h23 = __floats2half2_rn(c[2] * scl, c[3] * scl);
                *(__half2*)(D1 + row * NDIM + col)       = h01;
                *(__half2*)(D1 + (row + 8) * NDIM + col) = h23;
            }
        }
    }
}

// ---------------------------------------------------------------------------
// fp16 tensor-core attention (16 query rows/warp, 2 CTAs/SM), 128-key stages
// processed as two 64-key halves. Q pre-scaled by 0.125*log2(e) so
// P = ex2.approx(S) directly (no in-loop multiply).
// ---------------------------------------------------------------------------
#define HKS 72
#define KVSTG (2 * 128 * HKS)
#define NKBUF 3
#define HSM_BYTES (NKBUF * KVSTG * 2)        // 110592 B

__device__ __forceinline__ void attn_load_kv16(
    const __half* __restrict__ Kg, const __half* __restrict__ Vg,
    int t, uint32_t stg_base, int tid)
{
    const uint32_t kb = stg_base;
    const uint32_t vb = stg_base + 128 * HKS * 2;
#pragma unroll
    for (int i = 0; i < 4; i++) {
        int idx = tid + i * 256;
        int r = idx >> 3;
        int c = idx & 7;
        const uint32_t doff = (uint32_t)(r * HKS + c * 8) * 2;
        cp_async16(kb + doff, Kg + (size_t)(t * 128 + r) * 64 + c * 8);
        cp_async16(vb + doff, Vg + (size_t)(t * 128 + r) * 64 + c * 8);
    }
    cp_commit();
}

__global__ void __launch_bounds__(256, 2)
attn_fp16_kernel(const __half* __restrict__ Qh, const __half* __restrict__ Kh,
                 const __half* __restrict__ Vh, __half* __restrict__ Oh)
{
    extern __shared__ __half hsm[];
    const int tid = threadIdx.x;
    const int lane = tid & 31;
    const int w = tid >> 5;
    const int r0 = lane >> 2;
    const int c0 = lane & 3;
    const int h = blockIdx.y;
    const int b = blockIdx.z;
    const int qbase = blockIdx.x * 128;
    const size_t off = ((size_t)b * 2048 + h * 128) * 1024;

    const __half* Qg = Qh + off;
    const __half* Kg = Kh + off;
    const __half* Vg = Vh + off;
    const uint32_t sb = smem_u32(hsm);

    uint32_t qf[4][4];
    const int row0 = qbase + w * 16 + r0;
#pragma unroll
    for (int kg = 0; kg < 4; kg++)
#pragma unroll
        for (int q = 0; q < 4; q++) {
            int row = row0 + (q & 1) * 8;
            int col = kg * 16 + (q >> 1) * 8 + 2 * c0;
            qf[kg][q] = *(const uint32_t*)(Qg + (size_t)row * 64 + col);
        }

    float oacc[8][4];
#pragma unroll
    for (int nt = 0; nt < 8; nt++)
#pragma unroll
        for (int j = 0; j < 4; j++) oacc[nt][j] = 0.0f;
    float ls0 = 0.f, ls1 = 0.f;

    attn_load_kv16(Kg, Vg, 0, sb + 0 * KVSTG * 2, tid);
    attn_load_kv16(Kg, Vg, 1, sb + 1 * KVSTG * 2, tid);

    for (int t = 0; t < 16; t++) {
        if (t + 1 < 16) cp_wait<1>();
        else            cp_wait<0>();
        __syncthreads();
        if (t + 2 < 16)
            attn_load_kv16(Kg, Vg, t + 2, sb + ((t + 2) % NKBUF) * KVSTG * 2, tid);

        const uint32_t stg = sb + (uint32_t)((t % NKBUF) * KVSTG) * 2;

#pragma unroll
        for (int half = 0; half < 2; half++) {
            const uint32_t kbase = stg + (uint32_t)(half * 64 * HKS) * 2;
            const uint32_t vbase = stg + (uint32_t)(128 * HKS + half * 64 * HKS) * 2;

            // ---- S = Q @ K^T (Q pre-scaled) ----
            float sacc[8][4];
#pragma unroll
            for (int nt = 0; nt < 8; nt++)
#pragma unroll
                for (int j = 0; j < 4; j++) sacc[nt][j] = 0.0f;

#pragma unroll
            for (int nt = 0; nt < 8; nt++) {
                uint32_t bk[4][2];
#pragma unroll
                for (int p = 0; p < 2; p++) {
                    uint32_t a = kbase +
                        (uint32_t)((nt * 8 + (lane & 7)) * HKS + p * 32 + (lane >> 3) * 8) * 2;
                    ldsm_x4(bk[2 * p][0], bk[2 * p][1], bk[2 * p + 1][0], bk[2 * p + 1][1], a);
                }
#pragma unroll
                for (int kg = 0; kg < 4; kg++)
                    mma_f16(sacc[nt], qf[kg], bk[kg][0], bk[kg][1]);
            }

            // ---- P = 2^S: pack QK C-frags directly into PV A-frags ----
            uint32_t pfrag[4][4];
#pragma unroll
            for (int nt = 0; nt < 8; nt++) {
                float p0 = ex2f(sacc[nt][0]);
                float p1 = ex2f(sacc[nt][1]);
                float p2 = ex2f(sacc[nt][2]);
                float p3 = ex2f(sacc[nt][3]);
                ls0 += p0 + p1;
                ls1 += p2 + p3;
                __half2 h01 = __floats2half2_rn(p0, p1);
                __half2 h23 = __floats2half2_rn(p2, p3);
                pfrag[nt >> 1][(nt & 1) * 2 + 0] = *(uint32_t*)&h01;
                pfrag[nt >> 1][(nt & 1) * 2 + 1] = *(uint32_t*)&h23;
            }

            // ---- O += P @ V ----
#pragma unroll
            for (int kg = 0; kg < 4; kg++) {
#pragma unroll
                for (int p = 0; p < 4; p++) {
                    uint32_t bv0, bv1, bv2, bv3;
                    uint32_t a = vbase +
                        (uint32_t)((kg * 16 + ((lane >> 3) & 1) * 8 + (lane & 7)) * HKS +
                                   p * 16 + (lane >> 4) * 8) * 2;
                    ldsm_x4_t(bv0, bv1, bv2, bv3, a);
                    mma_f16(oacc[2 * p],     pfrag[kg], bv0, bv1);
                    mma_f16(oacc[2 * p + 1], pfrag[kg], bv2, bv3);
                }
            }
        }
    }

    ls0 += __shfl_xor_sync(0xffffffffu, ls0, 1);
    ls0 += __shfl_xor_sync(0xffffffffu, ls0, 2);
    ls1 += __shfl_xor_sync(0xffffffffu, ls1, 1);
    ls1 += __shfl_xor_sync(0xffffffffu, ls1, 2);
    const float inv0 = 1.0f / ls0;
    const float inv1 = 1.0f / ls1;

#pragma unroll
    for (int nt = 0; nt < 8; nt++) {
        const int col = h * 64 + nt * 8 + 2 * c0;
        __half2 hh01 = __floats2half2_rn(oacc[nt][0] * inv0, oacc[nt][1] * inv0);
        __half2 hh23 = __floats2half2_rn(oacc[nt][2] * inv1, oacc[nt][3] * inv1);
        *(__half2*)(Oh + ((size_t)(b * 2048 + row0)) * 1024 + col)     = hh01;
        *(__half2*)(Oh + ((size_t)(b * 2048 + row0 + 8)) * 1024 + col) = hh23;
    }
}

// ---------------------------------------------------------------------------
// Launch
// ---------------------------------------------------------------------------
extern "C" void kernel_launch(void* const* d_in, const int* in_sizes, int n_in,
                              void* d_out, int out_size)
{
    const float* Q  = (const float*)d_in[0];
    const float* K  = (const float*)d_in[1];
    const float* V  = (const float*)d_in[2];
    const float* WQ = (const float*)d_in[3];
    const float* WK = (const float*)d_in[4];
    const float* WV = (const float*)d_in[5];
    const float* Wf = (const float*)d_in[6];
    float* out = (float*)d_out;

    __half *X, *WT, *Qh, *Kh, *Vh;
    cudaGetSymbolAddress((void**)&X,  g_X);
    cudaGetSymbolAddress((void**)&WT, g_WT);
    cudaGetSymbolAddress((void**)&Qh, g_Qh);
    cudaGetSymbolAddress((void**)&Kh, g_Kh);
    cudaGetSymbolAddress((void**)&Vh, g_Vh);

    cudaFuncSetAttribute(gemm_f16_kernel,
                         cudaFuncAttributeMaxDynamicSharedMemorySize, GSMEM);
    cudaFuncSetAttribute(attn_fp16_kernel,
                         cudaFuncAttributeMaxDynamicSharedMemorySize, HSM_BYTES);

    const size_t NEL = (size_t)MDIM * NDIM;

    // 1) merged prepass: weights transpose->fp16 (z 0-3) + activations->fp16 (z 4-6)
    PrepArgs pr;
    pr.w[0] = WQ; pr.w[1] = WK; pr.w[2] = WV; pr.w[3] = Wf;
    pr.wt = WT;
    pr.x[0] = Q; pr.x[1] = K; pr.x[2] = V;
    for (int i = 0; i < 3; i++) pr.xd[i] = X + i * NEL;
    prep_kernel<<<dim3(32, 32, 7), dim3(32, 8)>>>(pr);

    // 2) Q/K/V projections -> fp16 (Q scaled by 0.125*log2e)
    GemmArgsH g1;
    for (int i = 0; i < 3; i++) {
        g1.A[i] = X + i * NEL;
        g1.B[i] = WT + (size_t)i * NDIM * KDIM;
        g1.C[i] = nullptr;
        g1.mode[i] = 2;
    }
    g1.D1[0] = Qh; g1.D1[1] = Kh; g1.D1[2] = Vh;
    g1.scale[0] = QSCALE; g1.scale[1] = 1.0f; g1.scale[2] = 1.0f;
    gemm_f16_kernel<<<dim3(NDIM / 128, MDIM / 128, 3), 256, GSMEM>>>(g1);

    // 3) attention -> ctx fp16 into slot 0
    attn_fp16_kernel<<<dim3(16, 16, 4), 256, HSM_BYTES>>>(Qh, Kh, Vh, X);

    // 4) output projection (f32 out)
    GemmArgsH g2;
    for (int i = 0; i < 3; i++) {
        g2.A[i] = X;
        g2.B[i] = WT + (size_t)3 * NDIM * KDIM;
        g2.C[i] = out;
        g2.D1[i] = nullptr;
        g2.scale[i] = 1.0f;
        g2.mode[i] = 0;
    }
    gemm_f16_kernel<<<dim3(NDIM / 128, MDIM / 128, 1), 256, GSMEM>>>(g2);
}

// round 15
// speedup vs baseline: 1.1510x; 1.0033x over previous
#include <cuda_runtime.h>
#include <cuda_fp16.h>
#include <cstdint>

// Shapes (fixed): B=4, S=2048, D=1024, H=16, dk=64.
#define MDIM 8192
#define NDIM 1024
#define KDIM 1024

// ---------------------------------------------------------------------------
// Device scratch (allocation-free per harness rules)
// ---------------------------------------------------------------------------
__device__ __half g_X[3][MDIM * NDIM];    // fp16 activations (slot 0 reused for ctx)
__device__ __half g_WT[4][NDIM * KDIM];   // transposed weights, fp16
__device__ __half g_Qh[MDIM * NDIM];      // fp16 projections for attention
__device__ __half g_Kh[MDIM * NDIM];
__device__ __half g_Vh[MDIM * NDIM];

// 0.125 * log2(e): folded into Q so attention uses bare ex2.approx
#define QSCALE 0.18033688011112042f

// ---------------------------------------------------------------------------
// Helpers
// ---------------------------------------------------------------------------
__device__ __forceinline__ uint32_t smem_u32(const void* p) {
    uint32_t a;
    asm("{ .reg .u64 t; cvta.to.shared.u64 t, %1; cvt.u32.u64 %0, t; }"
        : "=r"(a) : "l"(p));
    return a;
}

__device__ __forceinline__ float ex2f(float x) {
    float y;
    asm("ex2.approx.f32 %0, %1;" : "=f"(y) : "f"(x));
    return y;
}

__device__ __forceinline__ void mma_f16(float* c, const uint32_t* a,
                                        uint32_t b0, uint32_t b1) {
    asm volatile(
        "mma.sync.aligned.m16n8k16.row.col.f32.f16.f16.f32 "
        "{%0,%1,%2,%3}, {%4,%5,%6,%7}, {%8,%9}, {%0,%1,%2,%3};"
        : "+f"(c[0]), "+f"(c[1]), "+f"(c[2]), "+f"(c[3])
        : "r"(a[0]), "r"(a[1]), "r"(a[2]), "r"(a[3]), "r"(b0), "r"(b1));
}

__device__ __forceinline__ void ldsm_x4(uint32_t& d0, uint32_t& d1,
                                        uint32_t& d2, uint32_t& d3, uint32_t a) {
    asm volatile("ldmatrix.sync.aligned.m8n8.x4.shared.b16 {%0,%1,%2,%3}, [%4];"
                 : "=r"(d0), "=r"(d1), "=r"(d2), "=r"(d3) : "r"(a));
}
__device__ __forceinline__ void ldsm_x4_t(uint32_t& d0, uint32_t& d1,
                                          uint32_t& d2, uint32_t& d3, uint32_t a) {
    asm volatile("ldmatrix.sync.aligned.m8n8.x4.trans.shared.b16 {%0,%1,%2,%3}, [%4];"
                 : "=r"(d0), "=r"(d1), "=r"(d2), "=r"(d3) : "r"(a));
}

__device__ __forceinline__ void cp_async16(uint32_t dst, const void* src) {
    asm volatile("cp.async.cg.shared.global [%0], [%1], 16;"
                 :: "r"(dst), "l"(src) : "memory");
}
__device__ __forceinline__ void cp_commit() {
    asm volatile("cp.async.commit_group;" ::: "memory");
}
template <int N>
__device__ __forceinline__ void cp_wait() {
    asm volatile("cp.async.wait_group %0;" :: "n"(N) : "memory");
}

// ---------------------------------------------------------------------------
// Merged prepass: z<4 -> weight transpose to fp16; z>=4 -> activation convert.
// ---------------------------------------------------------------------------
struct PrepArgs {
    const float* w[4];
    __half* wt;
    const float* x[3];
    __half* xd[3];
};

__global__ __launch_bounds__(256) void prep_kernel(PrepArgs a)
{
    const int z = blockIdx.z;
    if (z < 4) {
        __shared__ float t[32][33];
        const float* W = a.w[z];
        __half* D = a.wt + (size_t)z * NDIM * KDIM;

        int x = blockIdx.x * 32 + threadIdx.x;
        int y0 = blockIdx.y * 32;
#pragma unroll
        for (int j = 0; j < 32; j += 8)
            t[threadIdx.y + j][threadIdx.x] =
                W[(size_t)(y0 + threadIdx.y + j) * 1024 + x];
        __syncthreads();
        int x2 = blockIdx.y * 32 + threadIdx.x;
        int y2 = blockIdx.x * 32;
#pragma unroll
        for (int j = 0; j < 32; j += 8)
            D[(size_t)(y2 + threadIdx.y + j) * 1024 + x2] =
                __float2half_rn(t[threadIdx.x][threadIdx.y + j]);
    } else {
        const float* X = a.x[z - 4];
        __half* H = a.xd[z - 4];
        const int tid = threadIdx.y * 32 + threadIdx.x;
        const size_t blk = (size_t)blockIdx.y * 32 + blockIdx.x;   // 0..1023
        size_t base = (blk * 256 + tid) * 4;
        const size_t stride = (size_t)1024 * 256 * 4;
#pragma unroll
        for (int it = 0; it < 8; it++) {
            size_t i = base + (size_t)it * stride;
            float4 v = *(const float4*)(X + i);
            __half2 h01 = __floats2half2_rn(v.x, v.y);
            __half2 h23 = __floats2half2_rn(v.z, v.w);
            uint2 pk;
            pk.x = *(uint32_t*)&h01;
            pk.y = *(uint32_t*)&h23;
            *(uint2*)(H + i) = pk;
        }
    }
}

// ---------------------------------------------------------------------------
// Single-pass fp16 mma.sync GEMM: C = A @ B^T, BK=64, 3-stage pipeline,
// CTA 128x128, 256 thr, 8 warps (2M x 4N), 2 CTAs/SM.
// Epilogue modes: 0: C f32;  2: D1 fp16 (scaled by args.scale[z])
// ---------------------------------------------------------------------------
#define WROW 36
#define TILEW (128 * WROW)
#define STW (2 * TILEW)
#define NBUF 3
#define GSMEM (NBUF * STW * 4)            // 110592 bytes

struct GemmArgsH {
    const __half *A[3], *B[3];
    float* C[3];
    __half* D1[3];
    float scale[3];
    int mode[3];
};

__device__ __forceinline__ void gemm_load_stage(
    const __half* __restrict__ A, const __half* __restrict__ B,
    int s, uint32_t sbase, int tid)
{
#pragma unroll
    for (int i = 0; i < 4; i++) {
        const int idx = tid + i * 256;
        const int r = idx >> 3;
        const int c = idx & 7;
        const uint32_t doff = (uint32_t)(r * WROW + c * 4) * 4;
        const size_t goff = (size_t)r * KDIM + s * 64 + c * 8;
        cp_async16(sbase + doff,             A + goff);
        cp_async16(sbase + TILEW * 4 + doff, B + goff);
    }
    cp_commit();
}

__global__ void __launch_bounds__(256, 2)
gemm_f16_kernel(GemmArgsH args)
{
    extern __shared__ uint32_t sw[];
    const int tid = threadIdx.x;
    const int lane = tid & 31;
    const int wid = tid >> 5;
    const int wm = wid >> 2;
    const int wn = wid & 3;
    const int r0 = lane >> 2;
    const int c0 = lane & 3;
    const int z = blockIdx.z;

    const size_t aoff = (size_t)blockIdx.y * 128 * KDIM;
    const size_t boff = (size_t)blockIdx.x * 128 * KDIM;
    const __half* A = args.A[z] + aoff;
    const __half* Bw = args.B[z] + boff;

    const uint32_t sbase = smem_u32(sw);

    float acc[4][4][4];
#pragma unroll
    for (int i = 0; i < 4; i++)
#pragma unroll
        for (int j = 0; j < 4; j++)
#pragma unroll
            for (int k = 0; k < 4; k++) acc[i][j][k] = 0.0f;

    gemm_load_stage(A, Bw, 0, sbase + 0 * STW * 4, tid);
    gemm_load_stage(A, Bw, 1, sbase + 1 * STW * 4, tid);

    const int NST = KDIM / 64;
    for (int s = 0; s < NST; s++) {
        if (s + 1 < NST) cp_wait<1>();
        else             cp_wait<0>();
        __syncthreads();
        if (s + 2 < NST)
            gemm_load_stage(A, Bw, s + 2, sbase + ((s + 2) % NBUF) * STW * 4, tid);
        const uint32_t* St = sw + (s % NBUF) * STW;

#pragma unroll
        for (int ks = 0; ks < 4; ks++) {
            uint32_t af[4][4], bf[4][2];
#pragma unroll
            for (int nt = 0; nt < 4; nt++) {
                const int n = wn * 32 + nt * 8 + r0;
                const int nb = TILEW + n * WROW + ks * 8 + c0;
                bf[nt][0] = St[nb];
                bf[nt][1] = St[nb + 4];
            }
#pragma unroll
            for (int mt = 0; mt < 4; mt++) {
                const int row = wm * 64 + mt * 16 + r0;
                const int base = row * WROW + ks * 8 + c0;
                af[mt][0] = St[base];
                af[mt][1] = St[base + 8 * WROW];
                af[mt][2] = St[base + 4];
                af[mt][3] = St[base + 8 * WROW + 4];
            }
#pragma unroll
            for (int mt = 0; mt < 4; mt++)
#pragma unroll
                for (int nt = 0; nt < 4; nt++)
                    mma_f16(acc[mt][nt], af[mt], bf[nt][0], bf[nt][1]);
        }
    }

    const int mode = args.mode[z];
    const float scl = args.scale[z];
    const size_t crow0 = (size_t)blockIdx.y * 128 + wm * 64;
    const size_t ccol0 = (size_t)blockIdx.x * 128 + wn * 32;
#pragma unroll
    for (int mt = 0; mt < 4; mt++) {
#pragma unroll
        for (int nt = 0; nt < 4; nt++) {
            const size_t row = crow0 + mt * 16 + r0;
            const size_t col = ccol0 + nt * 8 + c0 * 2;
            float* c = acc[mt][nt];
            if (mode == 0) {
                float* C = args.C[z];
                *(float2*)(C + row * NDIM + col)       = make_float2(c[0], c[1]);
                *(float2*)(C + (row + 8) * NDIM + col) = make_float2(c[2], c[3]);
            } else {
                __half* D1 = args.D1[z];
                __half2 h01 = __floats2half2_rn(c[0] * scl, c[1] * scl);
                __half2 h23 = __floats2half2_rn(c[2] * scl, c[3] * scl);
                *(__half2*)(D1 + row * NDIM + col)       = h01;
                *(__half2*)(D1 + (row + 8) * NDIM + col) = h23;
            }
        }
    }
}

// ---------------------------------------------------------------------------
// fp16 tensor-core attention (16 query rows/warp, 2 CTAs/SM), 128-key stages
// as two 64-key halves. Q pre-scaled -> P = ex2(S). Inner loops software-
// pipelined: K and V ldmatrix fragments double-buffered so LDSM latency is
// covered by the previous iteration's MMAs. Bit-identical to round 14.
// ---------------------------------------------------------------------------
#define HKS 72
#define KVSTG (2 * 128 * HKS)
#define NKBUF 3
#define HSM_BYTES (NKBUF * KVSTG * 2)        // 110592 B

__device__ __forceinline__ void attn_load_kv16(
    const __half* __restrict__ Kg, const __half* __restrict__ Vg,
    int t, uint32_t stg_base, int tid)
{
    const uint32_t kb = stg_base;
    const uint32_t vb = stg_base + 128 * HKS * 2;
#pragma unroll
    for (int i = 0; i < 4; i++) {
        int idx = tid + i * 256;
        int r = idx >> 3;
        int c = idx & 7;
        const uint32_t doff = (uint32_t)(r * HKS + c * 8) * 2;
        cp_async16(kb + doff, Kg + (size_t)(t * 128 + r) * 64 + c * 8);
        cp_async16(vb + doff, Vg + (size_t)(t * 128 + r) * 64 + c * 8);
    }
    cp_commit();
}

__global__ void __launch_bounds__(256, 2)
attn_fp16_kernel(const __half* __restrict__ Qh, const __half* __restrict__ Kh,
                 const __half* __restrict__ Vh, __half* __restrict__ Oh)
{
    extern __shared__ __half hsm[];
    const int tid = threadIdx.x;
    const int lane = tid & 31;
    const int w = tid >> 5;
    const int r0 = lane >> 2;
    const int c0 = lane & 3;
    const int h = blockIdx.y;
    const int b = blockIdx.z;
    const int qbase = blockIdx.x * 128;
    const size_t off = ((size_t)b * 2048 + h * 128) * 1024;

    const __half* Qg = Qh + off;
    const __half* Kg = Kh + off;
    const __half* Vg = Vh + off;
    const uint32_t sb = smem_u32(hsm);

    // lane-derived ldsm address components (hoisted)
    const uint32_t koff = (uint32_t)((lane & 7) * HKS + (lane >> 3) * 8) * 2;
    const uint32_t voff = (uint32_t)((((lane >> 3) & 1) * 8 + (lane & 7)) * HKS +
                                     (lane >> 4) * 8) * 2;

    uint32_t qf[4][4];
    const int row0 = qbase + w * 16 + r0;
#pragma unroll
    for (int kg = 0; kg < 4; kg++)
#pragma unroll
        for (int q = 0; q < 4; q++) {
            int row = row0 + (q & 1) * 8;
            int col = kg * 16 + (q >> 1) * 8 + 2 * c0;
            qf[kg][q] = *(const uint32_t*)(Qg + (size_t)row * 64 + col);
        }

    float oacc[8][4];
#pragma unroll
    for (int nt = 0; nt < 8; nt++)
#pragma unroll
        for (int j = 0; j < 4; j++) oacc[nt][j] = 0.0f;
    float ls0 = 0.f, ls1 = 0.f;

    attn_load_kv16(Kg, Vg, 0, sb + 0 * KVSTG * 2, tid);
    attn_load_kv16(Kg, Vg, 1, sb + 1 * KVSTG * 2, tid);

    for (int t = 0; t < 16; t++) {
        if (t + 1 < 16) cp_wait<1>();
        else            cp_wait<0>();
        __syncthreads();
        if (t + 2 < 16)
            attn_load_kv16(Kg, Vg, t + 2, sb + ((t + 2) % NKBUF) * KVSTG * 2, tid);

        const uint32_t stg = sb + (uint32_t)((t % NKBUF) * KVSTG) * 2;

#pragma unroll
        for (int half = 0; half < 2; half++) {
            const uint32_t kbase = stg + (uint32_t)(half * 64 * HKS) * 2 + koff;
            const uint32_t vbase = stg + (uint32_t)(128 * HKS + half * 64 * HKS) * 2 + voff;

            // ---- S = Q @ K^T : pipelined (double-buffered K fragments) ----
            float sacc[8][4];
#pragma unroll
            for (int nt = 0; nt < 8; nt++)
#pragma unroll
                for (int j = 0; j < 4; j++) sacc[nt][j] = 0.0f;

            uint32_t bk[2][4][2];
            // prologue: fragments for nt=0
            ldsm_x4(bk[0][0][0], bk[0][0][1], bk[0][1][0], bk[0][1][1],
                    kbase + 0);
            ldsm_x4(bk[0][2][0], bk[0][2][1], bk[0][3][0], bk[0][3][1],
                    kbase + 32 * 2);
#pragma unroll
            for (int nt = 0; nt < 8; nt++) {
                const int cur = nt & 1;
                if (nt < 7) {
                    const int nxt = cur ^ 1;
                    const uint32_t a = kbase + (uint32_t)((nt + 1) * 8 * HKS) * 2;
                    ldsm_x4(bk[nxt][0][0], bk[nxt][0][1], bk[nxt][1][0], bk[nxt][1][1],
                            a + 0);
                    ldsm_x4(bk[nxt][2][0], bk[nxt][2][1], bk[nxt][3][0], bk[nxt][3][1],
                            a + 32 * 2);
                }
#pragma unroll
                for (int kg = 0; kg < 4; kg++)
                    mma_f16(sacc[nt], qf[kg], bk[cur][kg][0], bk[cur][kg][1]);
            }

            // ---- P = 2^S: pack QK C-frags directly into PV A-frags ----
            uint32_t pfrag[4][4];
#pragma unroll
            for (int nt = 0; nt < 8; nt++) {
                float p0 = ex2f(sacc[nt][0]);
                float p1 = ex2f(sacc[nt][1]);
                float p2 = ex2f(sacc[nt][2]);
                float p3 = ex2f(sacc[nt][3]);
                ls0 += p0 + p1;
                ls1 += p2 + p3;
                __half2 h01 = __floats2half2_rn(p0, p1);
                __half2 h23 = __floats2half2_rn(p2, p3);
                pfrag[nt >> 1][(nt & 1) * 2 + 0] = *(uint32_t*)&h01;
                pfrag[nt >> 1][(nt & 1) * 2 + 1] = *(uint32_t*)&h23;
            }

            // ---- O += P @ V : pipelined (double-buffered V fragments) ----
            uint32_t bv[2][4];
            ldsm_x4_t(bv[0][0], bv[0][1], bv[0][2], bv[0][3], vbase);
#pragma unroll
            for (int idx = 0; idx < 16; idx++) {
                const int cur = idx & 1;
                if (idx < 15) {
                    const int ni = idx + 1;
                    const uint32_t a = vbase +
                        (uint32_t)(((ni >> 2) * 16) * HKS + (ni & 3) * 16) * 2;
                    ldsm_x4_t(bv[cur ^ 1][0], bv[cur ^ 1][1],
                              bv[cur ^ 1][2], bv[cur ^ 1][3], a);
                }
                const int kg = idx >> 2;
                const int p = idx & 3;
                mma_f16(oacc[2 * p],     pfrag[kg], bv[cur][0], bv[cur][1]);
                mma_f16(oacc[2 * p + 1], pfrag[kg], bv[cur][2], bv[cur][3]);
            }
        }
    }

    ls0 += __shfl_xor_sync(0xffffffffu, ls0, 1);
    ls0 += __shfl_xor_sync(0xffffffffu, ls0, 2);
    ls1 += __shfl_xor_sync(0xffffffffu, ls1, 1);
    ls1 += __shfl_xor_sync(0xffffffffu, ls1, 2);
    const float inv0 = 1.0f / ls0;
    const float inv1 = 1.0f / ls1;

#pragma unroll
    for (int nt = 0; nt < 8; nt++) {
        const int col = h * 64 + nt * 8 + 2 * c0;
        __half2 hh01 = __floats2half2_rn(oacc[nt][0] * inv0, oacc[nt][1] * inv0);
        __half2 hh23 = __floats2half2_rn(oacc[nt][2] * inv1, oacc[nt][3] * inv1);
        *(__half2*)(Oh + ((size_t)(b * 2048 + row0)) * 1024 + col)     = hh01;
        *(__half2*)(Oh + ((size_t)(b * 2048 + row0 + 8)) * 1024 + col) = hh23;
    }
}

// ---------------------------------------------------------------------------
// Launch
// ---------------------------------------------------------------------------
extern "C" void kernel_launch(void* const* d_in, const int* in_sizes, int n_in,
                              void* d_out, int out_size)
{
    const float* Q  = (const float*)d_in[0];
    const float* K  = (const float*)d_in[1];
    const float* V  = (const float*)d_in[2];
    const float* WQ = (const float*)d_in[3];
    const float* WK = (const float*)d_in[4];
    const float* WV = (const float*)d_in[5];
    const float* Wf = (const float*)d_in[6];
    float* out = (float*)d_out;

    __half *X, *WT, *Qh, *Kh, *Vh;
    cudaGetSymbolAddress((void**)&X,  g_X);
    cudaGetSymbolAddress((void**)&WT, g_WT);
    cudaGetSymbolAddress((void**)&Qh, g_Qh);
    cudaGetSymbolAddress((void**)&Kh, g_Kh);
    cudaGetSymbolAddress((void**)&Vh, g_Vh);

    cudaFuncSetAttribute(gemm_f16_kernel,
                         cudaFuncAttributeMaxDynamicSharedMemorySize, GSMEM);
    cudaFuncSetAttribute(attn_fp16_kernel,
                         cudaFuncAttributeMaxDynamicSharedMemorySize, HSM_BYTES);

    const size_t NEL = (size_t)MDIM * NDIM;

    // 1) merged prepass
    PrepArgs pr;
    pr.w[0] = WQ; pr.w[1] = WK; pr.w[2] = WV; pr.w[3] = Wf;
    pr.wt = WT;
    pr.x[0] = Q; pr.x[1] = K; pr.x[2] = V;
    for (int i = 0; i < 3; i++) pr.xd[i] = X + i * NEL;
    prep_kernel<<<dim3(32, 32, 7), dim3(32, 8)>>>(pr);

    // 2) Q/K/V projections -> fp16 (Q scaled by 0.125*log2e)
    GemmArgsH g1;
    for (int i = 0; i < 3; i++) {
        g1.A[i] = X + i * NEL;
        g1.B[i] = WT + (size_t)i * NDIM * KDIM;
        g1.C[i] = nullptr;
        g1.mode[i] = 2;
    }
    g1.D1[0] = Qh; g1.D1[1] = Kh; g1.D1[2] = Vh;
    g1.scale[0] = QSCALE; g1.scale[1] = 1.0f; g1.scale[2] = 1.0f;
    gemm_f16_kernel<<<dim3(NDIM / 128, MDIM / 128, 3), 256, GSMEM>>>(g1);

    // 3) attention -> ctx fp16 into slot 0
    attn_fp16_kernel<<<dim3(16, 16, 4), 256, HSM_BYTES>>>(Qh, Kh, Vh, X);

    // 4) output projection (f32 out)
    GemmArgsH g2;
    for (int i = 0; i < 3; i++) {
        g2.A[i] = X;
        g2.B[i] = WT + (size_t)3 * NDIM * KDIM;
        g2.C[i] = out;
        g2.D1[i] = nullptr;
        g2.scale[i] = 1.0f;
        g2.mode[i] = 0;
    }
    gemm_f16_kernel<<<dim3(NDIM / 128, MDIM / 128, 1), 256, GSMEM>>>(g2);
}